// round 11
// baseline (speedup 1.0000x reference)
#include <cuda_runtime.h>
#include <cuda_fp16.h>
#include <math.h>

#define Bb 4
#define Ss 4096
#define Hh 8
#define Dd 64
#define HD 512
#define NC 64
#define CS 64
#define BSn 16384
#define Mm 131072          // B*S*H rows
#define MD (Mm*64)         // 8.39M elems

// ---- fp32 scratch ----
__device__ float g_csum[MD];
__device__ float g_fg  [MD];
__device__ float g_igh [MD];
__device__ float g_cell[MD];
__device__ float g_ctot[Bb*NC*HD];
__device__ float g_a   [Bb*NC*HD];
__device__ float g_bv  [Bb*NC*HD];
__device__ int   g_flag[Bb*NC];
// ---- fp16 operand scratch ----
__device__ __half g_xh[MD];
__device__ __half g_lnh[MD];
__device__ __half g_ch[MD];
__device__ __half g_W1h[192*128];   // [c][k], gate-remapped
__device__ __half g_W2h[64*128];    // [n][k]

__device__ __forceinline__ float sigmf(float z){ return 1.f/(1.f+__expf(-z)); }

__device__ __forceinline__ void mma16(float* c, const unsigned* a, unsigned b0, unsigned b1){
    asm volatile("mma.sync.aligned.m16n8k16.row.col.f32.f16.f16.f32 "
        "{%0,%1,%2,%3}, {%4,%5,%6,%7}, {%8,%9}, {%0,%1,%2,%3};"
        : "+f"(c[0]),"+f"(c[1]),"+f"(c[2]),"+f"(c[3])
        : "r"(a[0]),"r"(a[1]),"r"(a[2]),"r"(a[3]), "r"(b0),"r"(b1));
}

// ---- P0: weight transpose + gate remap -> fp16 ----
__global__ void k_prepw(const float* __restrict__ W1, const float* __restrict__ W2){
    int c = blockIdx.x, k = threadIdx.x;
    if (c < 192){
        int wn=c/48, rem=c%48, gate=rem>>4, dd=rem&15;
        g_W1h[c*128+k] = __float2half(W1[k*192 + gate*64 + wn*16 + dd]);
    } else {
        int c2 = c-192;
        g_W2h[c2*128+k] = __float2half(W2[k*64 + c2]);
    }
}

// ---- K1: per-chunk totals + x -> fp16 ----
__global__ void k_chunksum(const float* __restrict__ x){
    int bc = blockIdx.x; int b = bc>>6; int c = bc&63; int t = threadIdx.x;
    int base = (b*Ss + c*CS)*HD + t;
    float acc = 0.f;
    #pragma unroll 8
    for (int s=0;s<CS;s++){
        float v = x[base + s*HD];
        acc += v;
        g_xh[base+s*HD] = __float2half(v);
    }
    g_ctot[bc*HD + t] = acc;
}

// ---- K2: exclusive scan of chunk totals (+ zero lookback flags) ----
__global__ void k_chunkscan(){
    int ch = blockIdx.x*blockDim.x + threadIdx.x;
    if (ch < Bb*NC) g_flag[ch] = 0;
    int b = ch>>9, t = ch&511;
    float run = 0.f;
    #pragma unroll
    for (int c=0;c<NC;c++){
        int i = (b*NC + c)*HD + t;
        float v = g_ctot[i]; g_ctot[i] = run; run += v;
    }
}

// ---- K3: materialize exclusive cumsum ----
__global__ void k_csum(const float* __restrict__ x){
    int bc = blockIdx.x; int b = bc>>6; int c = bc&63; int t = threadIdx.x;
    float run = g_ctot[bc*HD + t];
    int base = (b*Ss + c*CS)*HD + t;
    #pragma unroll 8
    for (int s=0;s<CS;s++){
        g_csum[base + s*HD] = run;
        run += x[base + s*HD];
    }
}

// ---- K4: LN stats + normalize -> fp16 (one warp per (b,s) row) ----
__global__ __launch_bounds__(512) void k_ln(const float* __restrict__ gamma,
                                            const float* __restrict__ beta){
    __shared__ float gsm[512], bsm[512];
    int t = threadIdx.x;
    gsm[t]=gamma[t]; bsm[t]=beta[t];
    __syncthreads();
    int lane = t&31;
    int row = blockIdx.x*16 + (t>>5);
    const float4* src = (const float4*)(g_csum + row*512);
    float4 v[4]; float s1=0.f, s2=0.f;
    #pragma unroll
    for (int i=0;i<4;i++){
        v[i] = src[i*32+lane];
        s1 += v[i].x+v[i].y+v[i].z+v[i].w;
        s2 += v[i].x*v[i].x+v[i].y*v[i].y+v[i].z*v[i].z+v[i].w*v[i].w;
    }
    #pragma unroll
    for (int o=16;o;o>>=1){
        s1 += __shfl_xor_sync(0xffffffffu, s1, o);
        s2 += __shfl_xor_sync(0xffffffffu, s2, o);
    }
    float mean = s1*(1.f/512.f);
    float rinv = rsqrtf(s2*(1.f/512.f) - mean*mean + 1e-5f);
    #pragma unroll
    for (int i=0;i<4;i++){
        int e0 = (i*32+lane)*4;
        float w0 = (v[i].x-mean)*rinv*gsm[e0  ]+bsm[e0  ];
        float w1 = (v[i].y-mean)*rinv*gsm[e0+1]+bsm[e0+1];
        float w2 = (v[i].z-mean)*rinv*gsm[e0+2]+bsm[e0+2];
        float w3 = (v[i].w-mean)*rinv*gsm[e0+3]+bsm[e0+3];
        __half2 p0 = __floats2half2_rn(w0,w1);
        __half2 p1 = __floats2half2_rn(w2,w3);
        uint2 u; u.x = *(unsigned*)&p0; u.y = *(unsigned*)&p1;
        ((uint2*)(g_lnh + row*512))[i*32+lane] = u;
    }
}

// ---- K5: GEMM1 fp16 mma, single-shot full-K staging, M64 x N96 ----
// smem padded stride 68 words (136 halfs): bank(lane)=lane -> conflict-free
__global__ __launch_bounds__(256) void k_gemm1(const float* __restrict__ bias){
    __shared__ __align__(16) unsigned As[64*68];
    __shared__ __align__(16) unsigned Bs[96*68];
    int t = threadIdx.x;
    int r0 = blockIdx.x*64;
    int y  = blockIdx.y;
    int lane=t&31, wid=t>>5, wm=wid&3, wn=wid>>2;
    int g=lane>>2, tg=lane&3;

    // stage A: rows r0..r0+63, K = [x(0:64) | ln(64:128)]
    {
        const uint4* xh4 = (const uint4*)g_xh;
        const uint4* ln4 = (const uint4*)g_lnh;
        uint4* Ad = (uint4*)As;
        #pragma unroll
        for (int i=0;i<4;i++){
            int idx = t + i*256;             // 0..1023
            int row = idx>>4, q = idx&15;    // 16 uint4 per row
            uint4 v = (q<8) ? xh4[(r0+row)*8 + q] : ln4[(r0+row)*8 + (q-8)];
            Ad[row*17 + q] = v;
        }
        const uint4* w4 = (const uint4*)g_W1h;
        uint4* Bd = (uint4*)Bs;
        #pragma unroll
        for (int i=0;i<6;i++){
            int idx = t + i*256;             // 0..1535
            int row = idx>>4, q = idx&15;
            Bd[row*17 + q] = w4[(96*y + row)*16 + q];
        }
    }
    __syncthreads();

    float Cr[6][4];
    #pragma unroll
    for (int b=0;b<6;b++)
        #pragma unroll
        for (int c=0;c<4;c++) Cr[b][c]=0.f;

    int mr = wm*16;
    #pragma unroll
    for (int ks=0;ks<8;ks++){
        unsigned a[4];
        a[0]=As[(mr+g  )*68 + ks*8 + tg  ];
        a[1]=As[(mr+g+8)*68 + ks*8 + tg  ];
        a[2]=As[(mr+g  )*68 + ks*8 + tg+4];
        a[3]=As[(mr+g+8)*68 + ks*8 + tg+4];
        #pragma unroll
        for (int nf=0;nf<6;nf++){
            int cb = wn*48 + nf*8 + g;
            unsigned b0=Bs[cb*68 + ks*8 + tg], b1=Bs[cb*68 + ks*8 + tg+4];
            mma16(Cr[nf], a, b0, b1);
        }
    }
    #pragma unroll
    for (int nfd=0;nfd<2;nfd++)
        #pragma unroll
        for (int j=0;j<4;j++){
            int row = r0 + mr + g + ((j>>1)<<3);
            int colf = 2*tg + (j&1);
            int d = (2*y + wn)*16 + nfd*8 + colf;
            float ig  = Cr[nfd  ][j] + __ldg(&bias[d]);
            float fgv = Cr[nfd+2][j] + __ldg(&bias[64+d]);
            float hd  = Cr[nfd+4][j] + __ldg(&bias[128+d]);
            g_fg [row*64+d] = sigmf(fgv);
            g_igh[row*64+d] = sigmf(ig)*fmaxf(hd,0.f);
        }
}

// ---- K6: single-pass decoupled-lookback scan -> cell (fp16 + fp32) ----
__global__ __launch_bounds__(512) void k_scan(const float* __restrict__ initcx){
    int bc = blockIdx.x; int b = bc>>6; int c = bc&63; int t = threadIdx.x;
    int base = (b*Ss + c*CS)*HD + t;

    float a = 1.f, bv = 0.f;
    #pragma unroll 8
    for (int s=0;s<CS;s++){
        float f = g_fg[base + s*HD];
        float g = g_igh[base + s*HD];
        a *= f; bv = bv*f + g;
    }
    g_a[bc*HD + t] = a; g_bv[bc*HD + t] = bv;
    __threadfence();
    __syncthreads();
    if (t==0) atomicExch(&g_flag[bc], 1);

    float cell = initcx[t];
    if (c > 0){
        if (t < c){
            volatile int* fl = &g_flag[b*64 + t];
            while (*fl == 0) { }
        }
        __syncthreads();
        __threadfence();
        for (int p=0;p<c;p++){
            int idx = (b*64 + p)*HD + t;
            cell = g_a[idx]*cell + g_bv[idx];
        }
    }

    #pragma unroll 4
    for (int s=0;s<CS;s++){
        float f = g_fg[base + s*HD];
        float g = g_igh[base + s*HD];
        cell = f*cell + g;
        g_cell[base+s*HD] = cell;
        g_ch[base+s*HD] = __float2half(cell);
    }
}

// ---- K7: GEMM2 fp16 mma, single-shot full-K, fused og*cell ----
__global__ __launch_bounds__(256) void k_gemm2(const float* __restrict__ bias,
                                               float* __restrict__ out){
    __shared__ __align__(16) unsigned As[64*68];
    __shared__ __align__(16) unsigned Bs[64*68];
    int t = threadIdx.x;
    int r0 = blockIdx.x*64;
    int lane=t&31, wid=t>>5, wm=wid&1, wn=wid>>1;
    int g=lane>>2, tg=lane&3;

    {
        const uint4* xh4 = (const uint4*)g_xh;
        const uint4* ch4 = (const uint4*)g_ch;
        uint4* Ad = (uint4*)As;
        const uint4* w4 = (const uint4*)g_W2h;
        uint4* Bd = (uint4*)Bs;
        #pragma unroll
        for (int i=0;i<4;i++){
            int idx = t + i*256;
            int row = idx>>4, q = idx&15;
            uint4 v = (q<8) ? xh4[(r0+row)*8 + q] : ch4[(r0+row)*8 + (q-8)];
            Ad[row*17 + q] = v;
            Bd[row*17 + q] = w4[row*16 + q];
        }
    }
    __syncthreads();

    float Cr[2][2][4];
    #pragma unroll
    for (int a=0;a<2;a++)
        #pragma unroll
        for (int b=0;b<2;b++)
            #pragma unroll
            for (int c=0;c<4;c++) Cr[a][b][c]=0.f;

    #pragma unroll
    for (int ks=0;ks<8;ks++){
        unsigned a[2][4];
        #pragma unroll
        for (int mf=0;mf<2;mf++){
            int mr = wm*32 + mf*16;
            a[mf][0]=As[(mr+g  )*68 + ks*8 + tg  ];
            a[mf][1]=As[(mr+g+8)*68 + ks*8 + tg  ];
            a[mf][2]=As[(mr+g  )*68 + ks*8 + tg+4];
            a[mf][3]=As[(mr+g+8)*68 + ks*8 + tg+4];
        }
        #pragma unroll
        for (int nf=0;nf<2;nf++){
            int cb = wn*16 + nf*8 + g;
            unsigned b0=Bs[cb*68 + ks*8 + tg], b1=Bs[cb*68 + ks*8 + tg+4];
            #pragma unroll
            for (int mf=0;mf<2;mf++)
                mma16(Cr[mf][nf], a[mf], b0, b1);
        }
    }
    #pragma unroll
    for (int mf=0;mf<2;mf++)
        #pragma unroll
        for (int nf=0;nf<2;nf++)
            #pragma unroll
            for (int j=0;j<4;j++){
                int row = r0 + wm*32 + mf*16 + g + ((j>>1)<<3);
                int col = wn*16 + nf*8 + 2*tg + (j&1);
                float og = sigmf(Cr[mf][nf][j] + __ldg(&bias[col]));
                out[row*64+col] = og * g_cell[row*64+col];
            }
}

extern "C" void kernel_launch(void* const* d_in, const int* in_sizes, int n_in,
                              void* d_out, int out_size){
    const float* x      = (const float*)d_in[0];
    const float* W_hid  = (const float*)d_in[1];
    const float* b_hid  = (const float*)d_in[2];
    const float* W_og   = (const float*)d_in[3];
    const float* b_og   = (const float*)d_in[4];
    const float* gamma  = (const float*)d_in[5];
    const float* beta   = (const float*)d_in[6];
    const float* initcx = (const float*)d_in[7];
    float* out = (float*)d_out;

    k_chunksum <<<Bb*NC, 512>>>(x);
    k_chunkscan<<<16, 128>>>();
    k_csum     <<<Bb*NC, 512>>>(x);
    k_ln       <<<BSn/16, 512>>>(gamma, beta);     // captured slot
    k_prepw    <<<256, 128>>>(W_hid, W_og);
    k_gemm1    <<<dim3(Mm/64, 2), 256>>>(b_hid);
    k_scan     <<<Bb*NC, 512>>>(initcx);
    k_gemm2    <<<Mm/64, 256>>>(b_og, out);
}

// round 12
// speedup vs baseline: 1.3226x; 1.3226x over previous
#include <cuda_runtime.h>
#include <cuda_fp16.h>
#include <math.h>

#define Bb 4
#define Ss 4096
#define Hh 8
#define Dd 64
#define HD 512
#define NC 64
#define CS 64
#define BSn 16384
#define Mm 131072          // B*S*H rows
#define MD (Mm*64)         // 8.39M elems

// ---- fp32 scratch ----
__device__ float g_csum[MD];
__device__ float g_fg  [MD];
__device__ float g_igh [MD];
__device__ float g_cell[MD];
__device__ float g_ctot[Bb*NC*HD];
__device__ float g_a   [Bb*NC*HD];
__device__ float g_bv  [Bb*NC*HD];
__device__ int   g_flag[Bb*NC];
// ---- fp16 operand scratch ----
__device__ __half g_xh[MD];
__device__ __half g_lnh[MD];
__device__ __half g_ch[MD];
__device__ __half g_W1h[192*128];   // [c][k], gate-remapped
__device__ __half g_W2h[64*128];    // [n][k]

__device__ __forceinline__ float sigmf(float z){ return 1.f/(1.f+__expf(-z)); }

__device__ __forceinline__ void mma16(float* c, const unsigned* a, unsigned b0, unsigned b1){
    asm volatile("mma.sync.aligned.m16n8k16.row.col.f32.f16.f16.f32 "
        "{%0,%1,%2,%3}, {%4,%5,%6,%7}, {%8,%9}, {%0,%1,%2,%3};"
        : "+f"(c[0]),"+f"(c[1]),"+f"(c[2]),"+f"(c[3])
        : "r"(a[0]),"r"(a[1]),"r"(a[2]),"r"(a[3]), "r"(b0),"r"(b1));
}

// ---- P0: weight transpose + gate remap -> fp16 ----
__global__ void k_prepw(const float* __restrict__ W1, const float* __restrict__ W2){
    int c = blockIdx.x, k = threadIdx.x;
    if (c < 192){
        int wn=c/48, rem=c%48, gate=rem>>4, dd=rem&15;
        g_W1h[c*128+k] = __float2half(W1[k*192 + gate*64 + wn*16 + dd]);
    } else {
        int c2 = c-192;
        g_W2h[c2*128+k] = __float2half(W2[k*64 + c2]);
    }
}

// ---- K1: per-chunk totals + x -> fp16 ----
__global__ void k_chunksum(const float* __restrict__ x){
    int bc = blockIdx.x; int b = bc>>6; int c = bc&63; int t = threadIdx.x;
    int base = (b*Ss + c*CS)*HD + t;
    float acc = 0.f;
    #pragma unroll 8
    for (int s=0;s<CS;s++){
        float v = x[base + s*HD];
        acc += v;
        g_xh[base+s*HD] = __float2half(v);
    }
    g_ctot[bc*HD + t] = acc;
}

// ---- K2: exclusive scan of chunk totals (+ zero lookback flags) ----
__global__ void k_chunkscan(){
    int ch = blockIdx.x*blockDim.x + threadIdx.x;
    if (ch < Bb*NC) g_flag[ch] = 0;
    int b = ch>>9, t = ch&511;
    float run = 0.f;
    #pragma unroll
    for (int c=0;c<NC;c++){
        int i = (b*NC + c)*HD + t;
        float v = g_ctot[i]; g_ctot[i] = run; run += v;
    }
}

// ---- K3: materialize exclusive cumsum ----
__global__ void k_csum(const float* __restrict__ x){
    int bc = blockIdx.x; int b = bc>>6; int c = bc&63; int t = threadIdx.x;
    float run = g_ctot[bc*HD + t];
    int base = (b*Ss + c*CS)*HD + t;
    #pragma unroll 8
    for (int s=0;s<CS;s++){
        g_csum[base + s*HD] = run;
        run += x[base + s*HD];
    }
}

// ---- K4: LN stats + normalize -> fp16 (one warp per (b,s) row) ----
__global__ __launch_bounds__(512) void k_ln(const float* __restrict__ gamma,
                                            const float* __restrict__ beta){
    __shared__ float gsm[512], bsm[512];
    int t = threadIdx.x;
    gsm[t]=gamma[t]; bsm[t]=beta[t];
    __syncthreads();
    int lane = t&31;
    int row = blockIdx.x*16 + (t>>5);
    const float4* src = (const float4*)(g_csum + row*512);
    float4 v[4]; float s1=0.f, s2=0.f;
    #pragma unroll
    for (int i=0;i<4;i++){
        v[i] = src[i*32+lane];
        s1 += v[i].x+v[i].y+v[i].z+v[i].w;
        s2 += v[i].x*v[i].x+v[i].y*v[i].y+v[i].z*v[i].z+v[i].w*v[i].w;
    }
    #pragma unroll
    for (int o=16;o;o>>=1){
        s1 += __shfl_xor_sync(0xffffffffu, s1, o);
        s2 += __shfl_xor_sync(0xffffffffu, s2, o);
    }
    float mean = s1*(1.f/512.f);
    float rinv = rsqrtf(s2*(1.f/512.f) - mean*mean + 1e-5f);
    #pragma unroll
    for (int i=0;i<4;i++){
        int e0 = (i*32+lane)*4;
        float w0 = (v[i].x-mean)*rinv*gsm[e0  ]+bsm[e0  ];
        float w1 = (v[i].y-mean)*rinv*gsm[e0+1]+bsm[e0+1];
        float w2 = (v[i].z-mean)*rinv*gsm[e0+2]+bsm[e0+2];
        float w3 = (v[i].w-mean)*rinv*gsm[e0+3]+bsm[e0+3];
        __half2 p0 = __floats2half2_rn(w0,w1);
        __half2 p1 = __floats2half2_rn(w2,w3);
        uint2 u; u.x = *(unsigned*)&p0; u.y = *(unsigned*)&p1;
        ((uint2*)(g_lnh + row*512))[i*32+lane] = u;
    }
}

// ---- K5: GEMM1 fp16 mma, k32 double-buffered stages, M64 x N96 ----
// smem stride 40 halfs (20 words): LDS banks (20g+tg) -> {0,4,..,28}+tg, conflict-free
__global__ __launch_bounds__(256,4) void k_gemm1(const float* __restrict__ bias){
    __shared__ __align__(16) __half Ah[2][64*40];
    __shared__ __align__(16) __half Bh[2][96*40];
    int t = threadIdx.x;
    int r0 = blockIdx.x*64;
    int y  = blockIdx.y;
    int lane=t&31, wid=t>>5, wm=wid&3, wn=wid>>2;
    int g=lane>>2, tg=lane&3;

    float Cr[6][4];
    #pragma unroll
    for (int b=0;b<6;b++)
        #pragma unroll
        for (int c=0;c<4;c++) Cr[b][c]=0.f;

    uint4 ra; uint2 rb[3];
    int arow = t>>2, aq = t&3;
    auto load_stage = [&](int s){
        const uint4* ga = (const uint4*)(s<2 ? g_xh : g_lnh);
        ra = ga[(r0+arow)*8 + (s&1)*4 + aq];
        const uint2* gb = (const uint2*)g_W1h;
        #pragma unroll
        for (int i=0;i<3;i++){
            int idx = t + i*256;              // 0..767
            int brow = idx>>3, c = idx&7;
            rb[i] = gb[(96*y + brow)*32 + s*8 + c];
        }
    };
    auto store_stage = [&](int buf){
        uint4* sa = (uint4*)Ah[buf];
        sa[arow*5 + aq] = ra;
        uint2* sbm = (uint2*)Bh[buf];
        #pragma unroll
        for (int i=0;i<3;i++){
            int idx = t + i*256;
            int brow = idx>>3, c = idx&7;
            sbm[brow*10 + c] = rb[i];
        }
    };

    load_stage(0); store_stage(0); __syncthreads();
    int mr = wm*16;
    for (int s=0;s<4;s++){
        int buf = s&1;
        if (s<3) load_stage(s+1);
        const unsigned* As = (const unsigned*)Ah[buf];
        const unsigned* Bs = (const unsigned*)Bh[buf];
        #pragma unroll
        for (int kk=0;kk<2;kk++){
            unsigned a[4];
            a[0]=As[(mr+g  )*20 + kk*8 + tg  ];
            a[1]=As[(mr+g+8)*20 + kk*8 + tg  ];
            a[2]=As[(mr+g  )*20 + kk*8 + tg+4];
            a[3]=As[(mr+g+8)*20 + kk*8 + tg+4];
            #pragma unroll
            for (int nf=0;nf<6;nf++){
                int cb = wn*48 + nf*8 + g;
                unsigned b0=Bs[cb*20 + kk*8 + tg], b1=Bs[cb*20 + kk*8 + tg+4];
                mma16(Cr[nf], a, b0, b1);
            }
        }
        if (s<3){ store_stage((s+1)&1); __syncthreads(); }
    }
    #pragma unroll
    for (int nfd=0;nfd<2;nfd++)
        #pragma unroll
        for (int j=0;j<4;j++){
            int row = r0 + mr + g + ((j>>1)<<3);
            int colf = 2*tg + (j&1);
            int d = (2*y + wn)*16 + nfd*8 + colf;
            float ig  = Cr[nfd  ][j] + __ldg(&bias[d]);
            float fgv = Cr[nfd+2][j] + __ldg(&bias[64+d]);
            float hd  = Cr[nfd+4][j] + __ldg(&bias[128+d]);
            g_fg [row*64+d] = sigmf(fgv);
            g_igh[row*64+d] = sigmf(ig)*fmaxf(hd,0.f);
        }
}

// ---- K6: single-pass decoupled-lookback scan -> cell (fp16 + fp32) ----
__global__ __launch_bounds__(512) void k_scan(const float* __restrict__ initcx){
    int bc = blockIdx.x; int b = bc>>6; int c = bc&63; int t = threadIdx.x;
    int base = (b*Ss + c*CS)*HD + t;

    float a = 1.f, bv = 0.f;
    #pragma unroll 8
    for (int s=0;s<CS;s++){
        float f = g_fg[base + s*HD];
        float g = g_igh[base + s*HD];
        a *= f; bv = bv*f + g;
    }
    g_a[bc*HD + t] = a; g_bv[bc*HD + t] = bv;
    __threadfence();
    __syncthreads();
    if (t==0) atomicExch(&g_flag[bc], 1);

    float cell = initcx[t];
    if (c > 0){
        if (t < c){
            volatile int* fl = &g_flag[b*64 + t];
            while (*fl == 0) { }
        }
        __syncthreads();
        __threadfence();
        for (int p=0;p<c;p++){
            int idx = (b*64 + p)*HD + t;
            cell = g_a[idx]*cell + g_bv[idx];
        }
    }

    #pragma unroll 4
    for (int s=0;s<CS;s++){
        float f = g_fg[base + s*HD];
        float g = g_igh[base + s*HD];
        cell = f*cell + g;
        g_cell[base+s*HD] = cell;
        g_ch[base+s*HD] = __float2half(cell);
    }
}

// ---- K7: GEMM2 fp16 mma, k32 stages, fused og*cell ----
__global__ __launch_bounds__(256,4) void k_gemm2(const float* __restrict__ bias,
                                                 float* __restrict__ out){
    __shared__ __align__(16) __half Ah[2][64*40];
    __shared__ __align__(16) __half Bh[2][64*40];
    int t = threadIdx.x;
    int r0 = blockIdx.x*64;
    int lane=t&31, wid=t>>5, wm=wid&1, wn=wid>>1;
    int g=lane>>2, tg=lane&3;

    float Cr[2][2][4];
    #pragma unroll
    for (int a=0;a<2;a++)
        #pragma unroll
        for (int b=0;b<2;b++)
            #pragma unroll
            for (int c=0;c<4;c++) Cr[a][b][c]=0.f;

    uint4 ra, rb;
    int arow = t>>2, aq = t&3;
    auto load_stage = [&](int s){
        const uint4* ga = (const uint4*)(s<2 ? g_xh : g_ch);
        ra = ga[(r0+arow)*8 + (s&1)*4 + aq];
        const uint4* gb = (const uint4*)g_W2h;
        rb = gb[arow*16 + s*4 + aq];
    };
    auto store_stage = [&](int buf){
        ((uint4*)Ah[buf])[arow*5 + aq] = ra;
        ((uint4*)Bh[buf])[arow*5 + aq] = rb;
    };

    load_stage(0); store_stage(0); __syncthreads();
    for (int s=0;s<4;s++){
        int buf = s&1;
        if (s<3) load_stage(s+1);
        const unsigned* As = (const unsigned*)Ah[buf];
        const unsigned* Bs = (const unsigned*)Bh[buf];
        #pragma unroll
        for (int kk=0;kk<2;kk++){
            unsigned a[2][4];
            #pragma unroll
            for (int mf=0;mf<2;mf++){
                int mr = wm*32 + mf*16;
                a[mf][0]=As[(mr+g  )*20 + kk*8 + tg  ];
                a[mf][1]=As[(mr+g+8)*20 + kk*8 + tg  ];
                a[mf][2]=As[(mr+g  )*20 + kk*8 + tg+4];
                a[mf][3]=As[(mr+g+8)*20 + kk*8 + tg+4];
            }
            #pragma unroll
            for (int nf=0;nf<2;nf++){
                int cb = wn*16 + nf*8 + g;
                unsigned b0=Bs[cb*20 + kk*8 + tg], b1=Bs[cb*20 + kk*8 + tg+4];
                #pragma unroll
                for (int mf=0;mf<2;mf++)
                    mma16(Cr[mf][nf], a[mf], b0, b1);
            }
        }
        if (s<3){ store_stage((s+1)&1); __syncthreads(); }
    }
    #pragma unroll
    for (int mf=0;mf<2;mf++)
        #pragma unroll
        for (int nf=0;nf<2;nf++)
            #pragma unroll
            for (int j=0;j<4;j++){
                int row = r0 + wm*32 + mf*16 + g + ((j>>1)<<3);
                int col = wn*16 + nf*8 + 2*tg + (j&1);
                float og = sigmf(Cr[mf][nf][j] + __ldg(&bias[col]));
                out[row*64+col] = og * g_cell[row*64+col];
            }
}

extern "C" void kernel_launch(void* const* d_in, const int* in_sizes, int n_in,
                              void* d_out, int out_size){
    const float* x      = (const float*)d_in[0];
    const float* W_hid  = (const float*)d_in[1];
    const float* b_hid  = (const float*)d_in[2];
    const float* W_og   = (const float*)d_in[3];
    const float* b_og   = (const float*)d_in[4];
    const float* gamma  = (const float*)d_in[5];
    const float* beta   = (const float*)d_in[6];
    const float* initcx = (const float*)d_in[7];
    float* out = (float*)d_out;

    k_chunksum <<<Bb*NC, 512>>>(x);
    k_chunkscan<<<16, 128>>>();
    k_csum     <<<Bb*NC, 512>>>(x);
    k_ln       <<<BSn/16, 512>>>(gamma, beta);     // captured slot
    k_prepw    <<<256, 128>>>(W_hid, W_og);
    k_gemm1    <<<dim3(Mm/64, 2), 256>>>(b_hid);
    k_scan     <<<Bb*NC, 512>>>(initcx);
    k_gemm2    <<<Mm/64, 256>>>(b_og, out);
}

// round 13
// speedup vs baseline: 1.6514x; 1.2486x over previous
#include <cuda_runtime.h>
#include <cuda_fp16.h>
#include <math.h>

#define Bb 4
#define Ss 4096
#define Hh 8
#define Dd 64
#define HD 512
#define NC 64
#define CS 64
#define BSn 16384
#define Mm 131072          // B*S*H rows
#define MD (Mm*64)         // 8.39M elems

// ---- fp32 scratch ----
__device__ float g_csum[MD];          // chunk-LOCAL exclusive cumsum
__device__ float g_fg  [MD];
__device__ float g_igh [MD];
__device__ float g_ctot[Bb*NC*HD];
__device__ float g_a   [Bb*NC*HD];
__device__ float g_bv  [Bb*NC*HD];
__device__ int   g_flag[Bb*NC];
// ---- fp16 operand scratch ----
__device__ __half g_xh[MD];
__device__ __half g_lnh[MD];
__device__ __half g_ch[MD];
__device__ __half g_W1h[192*128];   // [c][k], gate-remapped
__device__ __half g_W2h[64*128];    // [n][k]

__device__ __forceinline__ float sigmf(float z){ return 1.f/(1.f+__expf(-z)); }

__device__ __forceinline__ void mma16(float* c, const unsigned* a, unsigned b0, unsigned b1){
    asm volatile("mma.sync.aligned.m16n8k16.row.col.f32.f16.f16.f32 "
        "{%0,%1,%2,%3}, {%4,%5,%6,%7}, {%8,%9}, {%0,%1,%2,%3};"
        : "+f"(c[0]),"+f"(c[1]),"+f"(c[2]),"+f"(c[3])
        : "r"(a[0]),"r"(a[1]),"r"(a[2]),"r"(a[3]), "r"(b0),"r"(b1));
}

// ---- K1: per-chunk totals + local exclusive cumsum + x -> fp16 ----
__global__ void k_chunksum(const float* __restrict__ x){
    int bc = blockIdx.x; int b = bc>>6; int c = bc&63; int t = threadIdx.x;
    int base = (b*Ss + c*CS)*HD + t;
    float acc = 0.f;
    #pragma unroll 8
    for (int s=0;s<CS;s++){
        float v = x[base + s*HD];
        g_csum[base + s*HD] = acc;      // local exclusive cumsum
        acc += v;
        g_xh[base+s*HD] = __float2half(v);
    }
    g_ctot[bc*HD + t] = acc;
}

// ---- K2: exclusive scan of chunk totals + flag zero + fused weight prep ----
__global__ void k_chunkscan(const float* __restrict__ W1, const float* __restrict__ W2){
    if (blockIdx.x >= 16){
        int c = blockIdx.x - 16, k = threadIdx.x;   // 256 blocks of prep work
        if (c < 192){
            int wn=c/48, rem=c%48, gate=rem>>4, dd=rem&15;
            g_W1h[c*128+k] = __float2half(W1[k*192 + gate*64 + wn*16 + dd]);
        } else {
            int c2 = c-192;
            g_W2h[c2*128+k] = __float2half(W2[k*64 + c2]);
        }
        return;
    }
    int ch = blockIdx.x*blockDim.x + threadIdx.x;
    if (ch < Bb*NC) g_flag[ch] = 0;
    int b = ch>>9, t = ch&511;
    float run = 0.f;
    #pragma unroll
    for (int c=0;c<NC;c++){
        int i = (b*NC + c)*HD + t;
        float v = g_ctot[i]; g_ctot[i] = run; run += v;
    }
}

// ---- K3: LN stats + normalize -> fp16 (one warp per (b,s) row) ----
// reads local csum + chunk offset from g_ctot (L2-resident)
__global__ __launch_bounds__(512) void k_ln(const float* __restrict__ gamma,
                                            const float* __restrict__ beta){
    __shared__ float gsm[512], bsm[512];
    int t = threadIdx.x;
    gsm[t]=gamma[t]; bsm[t]=beta[t];
    __syncthreads();
    int lane = t&31;
    int row = blockIdx.x*16 + (t>>5);
    int b = row>>12, s = row&4095, cch = s>>6;
    const float4* src = (const float4*)(g_csum + row*512);
    const float4* off = (const float4*)(g_ctot + ((b<<6)+cch)*512);
    float4 v[4]; float s1=0.f, s2=0.f;
    #pragma unroll
    for (int i=0;i<4;i++){
        float4 a = src[i*32+lane];
        float4 o = off[i*32+lane];
        v[i].x = a.x+o.x; v[i].y = a.y+o.y; v[i].z = a.z+o.z; v[i].w = a.w+o.w;
        s1 += v[i].x+v[i].y+v[i].z+v[i].w;
        s2 += v[i].x*v[i].x+v[i].y*v[i].y+v[i].z*v[i].z+v[i].w*v[i].w;
    }
    #pragma unroll
    for (int o=16;o;o>>=1){
        s1 += __shfl_xor_sync(0xffffffffu, s1, o);
        s2 += __shfl_xor_sync(0xffffffffu, s2, o);
    }
    float mean = s1*(1.f/512.f);
    float rinv = rsqrtf(s2*(1.f/512.f) - mean*mean + 1e-5f);
    #pragma unroll
    for (int i=0;i<4;i++){
        int e0 = (i*32+lane)*4;
        float w0 = (v[i].x-mean)*rinv*gsm[e0  ]+bsm[e0  ];
        float w1 = (v[i].y-mean)*rinv*gsm[e0+1]+bsm[e0+1];
        float w2 = (v[i].z-mean)*rinv*gsm[e0+2]+bsm[e0+2];
        float w3 = (v[i].w-mean)*rinv*gsm[e0+3]+bsm[e0+3];
        __half2 p0 = __floats2half2_rn(w0,w1);
        __half2 p1 = __floats2half2_rn(w2,w3);
        uint2 u; u.x = *(unsigned*)&p0; u.y = *(unsigned*)&p1;
        ((uint2*)(g_lnh + row*512))[i*32+lane] = u;
    }
}

// ---- K4: GEMM1 fp16 mma, k32 double-buffered stages, M64 x N96 ----
__global__ __launch_bounds__(256,4) void k_gemm1(const float* __restrict__ bias){
    __shared__ __align__(16) __half Ah[2][64*40];
    __shared__ __align__(16) __half Bh[2][96*40];
    int t = threadIdx.x;
    int r0 = blockIdx.x*64;
    int y  = blockIdx.y;
    int lane=t&31, wid=t>>5, wm=wid&3, wn=wid>>2;
    int g=lane>>2, tg=lane&3;

    float Cr[6][4];
    #pragma unroll
    for (int b=0;b<6;b++)
        #pragma unroll
        for (int c=0;c<4;c++) Cr[b][c]=0.f;

    uint4 ra; uint2 rb[3];
    int arow = t>>2, aq = t&3;
    auto load_stage = [&](int s){
        const uint4* ga = (const uint4*)(s<2 ? g_xh : g_lnh);
        ra = ga[(r0+arow)*8 + (s&1)*4 + aq];
        const uint2* gb = (const uint2*)g_W1h;
        #pragma unroll
        for (int i=0;i<3;i++){
            int idx = t + i*256;
            int brow = idx>>3, c = idx&7;
            rb[i] = gb[(96*y + brow)*32 + s*8 + c];
        }
    };
    auto store_stage = [&](int buf){
        uint4* sa = (uint4*)Ah[buf];
        sa[arow*5 + aq] = ra;
        uint2* sbm = (uint2*)Bh[buf];
        #pragma unroll
        for (int i=0;i<3;i++){
            int idx = t + i*256;
            int brow = idx>>3, c = idx&7;
            sbm[brow*10 + c] = rb[i];
        }
    };

    load_stage(0); store_stage(0); __syncthreads();
    int mr = wm*16;
    for (int s=0;s<4;s++){
        int buf = s&1;
        if (s<3) load_stage(s+1);
        const unsigned* As = (const unsigned*)Ah[buf];
        const unsigned* Bs = (const unsigned*)Bh[buf];
        #pragma unroll
        for (int kk=0;kk<2;kk++){
            unsigned a[4];
            a[0]=As[(mr+g  )*20 + kk*8 + tg  ];
            a[1]=As[(mr+g+8)*20 + kk*8 + tg  ];
            a[2]=As[(mr+g  )*20 + kk*8 + tg+4];
            a[3]=As[(mr+g+8)*20 + kk*8 + tg+4];
            #pragma unroll
            for (int nf=0;nf<6;nf++){
                int cb = wn*48 + nf*8 + g;
                unsigned b0=Bs[cb*20 + kk*8 + tg], b1=Bs[cb*20 + kk*8 + tg+4];
                mma16(Cr[nf], a, b0, b1);
            }
        }
        if (s<3){ store_stage((s+1)&1); __syncthreads(); }
    }
    #pragma unroll
    for (int nfd=0;nfd<2;nfd++)
        #pragma unroll
        for (int j=0;j<4;j++){
            int row = r0 + mr + g + ((j>>1)<<3);
            int colf = 2*tg + (j&1);
            int d = (2*y + wn)*16 + nfd*8 + colf;
            float ig  = Cr[nfd  ][j] + __ldg(&bias[d]);
            float fgv = Cr[nfd+2][j] + __ldg(&bias[64+d]);
            float hd  = Cr[nfd+4][j] + __ldg(&bias[128+d]);
            g_fg [row*64+d] = sigmf(fgv);
            g_igh[row*64+d] = sigmf(ig)*fmaxf(hd,0.f);
        }
}

// ---- K5: single-pass decoupled-lookback scan -> cell fp16 only ----
__global__ __launch_bounds__(512) void k_scan(const float* __restrict__ initcx){
    int bc = blockIdx.x; int b = bc>>6; int c = bc&63; int t = threadIdx.x;
    int base = (b*Ss + c*CS)*HD + t;

    float a = 1.f, bv = 0.f;
    #pragma unroll 8
    for (int s=0;s<CS;s++){
        float f = g_fg[base + s*HD];
        float g = g_igh[base + s*HD];
        a *= f; bv = bv*f + g;
    }
    g_a[bc*HD + t] = a; g_bv[bc*HD + t] = bv;
    __threadfence();
    __syncthreads();
    if (t==0) atomicExch(&g_flag[bc], 1);

    float cell = initcx[t];
    if (c > 0){
        if (t < c){
            volatile int* fl = &g_flag[b*64 + t];
            while (*fl == 0) { }
        }
        __syncthreads();
        __threadfence();
        for (int p=0;p<c;p++){
            int idx = (b*64 + p)*HD + t;
            cell = g_a[idx]*cell + g_bv[idx];
        }
    }

    #pragma unroll 4
    for (int s=0;s<CS;s++){
        float f = g_fg[base + s*HD];
        float g = g_igh[base + s*HD];
        cell = f*cell + g;
        g_ch[base+s*HD] = __float2half(cell);
    }
}

// ---- K6: GEMM2 fp16 mma, k32 stages, fused og*cell (cell from resident smem) ----
__global__ __launch_bounds__(256,4) void k_gemm2(const float* __restrict__ bias,
                                                 float* __restrict__ out){
    __shared__ __align__(16) __half Ah[2][64*40];
    __shared__ __align__(16) __half Bh[2][64*40];
    int t = threadIdx.x;
    int r0 = blockIdx.x*64;
    int lane=t&31, wid=t>>5, wm=wid&1, wn=wid>>1;
    int g=lane>>2, tg=lane&3;

    float Cr[2][2][4];
    #pragma unroll
    for (int a=0;a<2;a++)
        #pragma unroll
        for (int b=0;b<2;b++)
            #pragma unroll
            for (int c=0;c<4;c++) Cr[a][b][c]=0.f;

    uint4 ra, rb;
    int arow = t>>2, aq = t&3;
    auto load_stage = [&](int s){
        const uint4* ga = (const uint4*)(s<2 ? g_xh : g_ch);
        ra = ga[(r0+arow)*8 + (s&1)*4 + aq];
        const uint4* gb = (const uint4*)g_W2h;
        rb = gb[arow*16 + s*4 + aq];
    };
    auto store_stage = [&](int buf){
        ((uint4*)Ah[buf])[arow*5 + aq] = ra;
        ((uint4*)Bh[buf])[arow*5 + aq] = rb;
    };

    load_stage(0); store_stage(0); __syncthreads();
    for (int s=0;s<4;s++){
        int buf = s&1;
        if (s<3) load_stage(s+1);
        const unsigned* As = (const unsigned*)Ah[buf];
        const unsigned* Bs = (const unsigned*)Bh[buf];
        #pragma unroll
        for (int kk=0;kk<2;kk++){
            unsigned a[2][4];
            #pragma unroll
            for (int mf=0;mf<2;mf++){
                int mr = wm*32 + mf*16;
                a[mf][0]=As[(mr+g  )*20 + kk*8 + tg  ];
                a[mf][1]=As[(mr+g+8)*20 + kk*8 + tg  ];
                a[mf][2]=As[(mr+g  )*20 + kk*8 + tg+4];
                a[mf][3]=As[(mr+g+8)*20 + kk*8 + tg+4];
            }
            #pragma unroll
            for (int nf=0;nf<2;nf++){
                int cb = wn*16 + nf*8 + g;
                unsigned b0=Bs[cb*20 + kk*8 + tg], b1=Bs[cb*20 + kk*8 + tg+4];
                #pragma unroll
                for (int mf=0;mf<2;mf++)
                    mma16(Cr[mf][nf], a[mf], b0, b1);
            }
        }
        if (s<3){ store_stage((s+1)&1); __syncthreads(); }
    }
    // cell tile (fp16) is still resident: stage2 (cols 0..31) in buf0, stage3 in buf1
    #pragma unroll
    for (int mf=0;mf<2;mf++)
        #pragma unroll
        for (int nf=0;nf<2;nf++)
            #pragma unroll
            for (int j=0;j<4;j++){
                int rl  = wm*32 + mf*16 + g + ((j>>1)<<3);
                int col = wn*16 + nf*8 + 2*tg + (j&1);
                float og = sigmf(Cr[mf][nf][j] + __ldg(&bias[col]));
                float cell = __half2float(Ah[col>>5][rl*40 + (col&31)]);
                out[(r0+rl)*64+col] = og * cell;
            }
}

extern "C" void kernel_launch(void* const* d_in, const int* in_sizes, int n_in,
                              void* d_out, int out_size){
    const float* x      = (const float*)d_in[0];
    const float* W_hid  = (const float*)d_in[1];
    const float* b_hid  = (const float*)d_in[2];
    const float* W_og   = (const float*)d_in[3];
    const float* b_og   = (const float*)d_in[4];
    const float* gamma  = (const float*)d_in[5];
    const float* beta   = (const float*)d_in[6];
    const float* initcx = (const float*)d_in[7];
    float* out = (float*)d_out;

    k_chunksum <<<Bb*NC, 512>>>(x);
    k_chunkscan<<<16+256, 128>>>(W_hid, W_og);
    k_ln       <<<BSn/16, 512>>>(gamma, beta);
    k_gemm1    <<<dim3(Mm/64, 2), 256>>>(b_hid);   // profiled slot 4
    k_scan     <<<Bb*NC, 512>>>(initcx);
    k_gemm2    <<<Mm/64, 256>>>(b_og, out);
}